// round 7
// baseline (speedup 1.0000x reference)
#include <cuda_runtime.h>
#include <cuda_bf16.h>
#include <stdint.h>

#define D             128
#define TWO_D         256
#define WARPS         8
#define THREADS       (WARPS * 32)
#define BLOCKS        760              // 152 SMs x 5 blocks/SM -> single full wave
#define TOTAL_WARPS   (BLOCKS * WARPS) // 6080
#define STAGES        10               // smem ring slots per warp (512B each)
#define DEPTH         9                // pipeline depth (outstanding rows)

__global__ void zero_out_kernel(float4* __restrict__ out, int n4) {
    int i = blockIdx.x * blockDim.x + threadIdx.x;
    if (i < n4) out[i] = make_float4(0.f, 0.f, 0.f, 0.f);
}

__device__ __forceinline__ void cp_async16(void* smem_dst, const void* gmem_src) {
    uint32_t s = (uint32_t)__cvta_generic_to_shared(smem_dst);
    asm volatile("cp.async.cg.shared.global [%0], [%1], 16;\n"
                 :: "r"(s), "l"(gmem_src) : "memory");
}
__device__ __forceinline__ void cp_commit() {
    asm volatile("cp.async.commit_group;\n" ::: "memory");
}
__device__ __forceinline__ void cp_wait_allow8() {
    asm volatile("cp.async.wait_group 8;\n" ::: "memory");
}

__device__ __forceinline__ void flush_acc(float* __restrict__ out, int b, int lane4,
                                          float4& a0, float4& a1) {
    float* p0 = out + (size_t)b * TWO_D + lane4;
    atomicAdd(p0 + 0, a0.x);
    atomicAdd(p0 + 1, a0.y);
    atomicAdd(p0 + 2, a0.z);
    atomicAdd(p0 + 3, a0.w);
    float* p1 = p0 + D;
    atomicAdd(p1 + 0, a1.x);
    atomicAdd(p1 + 1, a1.y);
    atomicAdd(p1 + 2, a1.z);
    atomicAdd(p1 + 3, a1.w);
    a0 = make_float4(0.f, 0.f, 0.f, 0.f);
    a1 = make_float4(0.f, 0.f, 0.f, 0.f);
}

__global__ __launch_bounds__(THREADS, 5)
void pool_kernel(const float* __restrict__ node_rep,
                 const int*   __restrict__ batch_ids,
                 const int*   __restrict__ mol_idx,
                 float*       __restrict__ out,
                 int n_rows,
                 int rows_per_warp) {
    __shared__ float4 buf[WARPS][STAGES][32];   // 40 KB

    const int warp  = threadIdx.x >> 5;
    const int lane  = threadIdx.x & 31;
    const int lane4 = lane << 2;

    const int gwarp = blockIdx.x * WARPS + warp;
    int cs = gwarp * rows_per_warp;
    int ce = cs + rows_per_warp;
    if (cs >= n_rows) return;
    if (ce > n_rows) ce = n_rows;
    const int nchunk = ce - cs;

    const float4* nr = reinterpret_cast<const float4*>(node_rep);

    // ---- prologue: fill pipeline to DEPTH outstanding groups ----
    int issued = 0;
    #pragma unroll
    for (int s = 0; s < DEPTH; s++) {
        if (issued < nchunk) {
            cp_async16(&buf[warp][s][lane],
                       nr + (size_t)(cs + issued) * (D / 4) + lane);
            issued++;
        }
        cp_commit();    // empty groups keep the group-count invariant
    }

    float4 acc0 = make_float4(0.f, 0.f, 0.f, 0.f);
    float4 acc1 = make_float4(0.f, 0.f, 0.f, 0.f);
    int cur_b = -1;

    // ---- main loop: one row per iteration, DEPTH rows in flight ----
    for (int i = 0; i < nchunk; i++) {
        // metadata early (independent L1/L2 hits, overlap with wait)
        const int b = __ldg(batch_ids + cs + i);
        const int m = __ldg(mol_idx   + cs + i);

        cp_wait_allow8();                      // row i's group now complete
        const float4 v = buf[warp][i % STAGES][lane];

        // prefetch row i+DEPTH into slot (i+DEPTH)%STAGES (never the slot just read)
        if (issued < nchunk) {
            cp_async16(&buf[warp][(i + DEPTH) % STAGES][lane],
                       nr + (size_t)(cs + issued) * (D / 4) + lane);
            issued++;
        }
        cp_commit();

        if (b != cur_b) {                      // rare: graph boundary
            if (cur_b >= 0) flush_acc(out, cur_b, lane4, acc0, acc1);
            cur_b = b;
        }
        if (m == 0) {                          // warp-uniform, non-divergent
            acc0.x += v.x; acc0.y += v.y; acc0.z += v.z; acc0.w += v.w;
        } else {
            acc1.x += v.x; acc1.y += v.y; acc1.z += v.z; acc1.w += v.w;
        }
    }

    if (cur_b >= 0) flush_acc(out, cur_b, lane4, acc0, acc1);
}

extern "C" void kernel_launch(void* const* d_in, const int* in_sizes, int n_in,
                              void* d_out, int out_size) {
    const float* node_rep  = (const float*)d_in[0];
    const int*   batch_ids = (const int*)  d_in[1];
    const int*   mol_idx   = (const int*)  d_in[2];
    float*       out       = (float*)      d_out;

    const int n_rows = in_sizes[1];

    int rpw = (n_rows + TOTAL_WARPS - 1) / TOTAL_WARPS;
    rpw = (rpw + 3) & ~3;

    {
        int n4 = out_size / 4;
        int threads = 256;
        int blocks  = (n4 + threads - 1) / threads;
        zero_out_kernel<<<blocks, threads>>>((float4*)out, n4);
    }
    pool_kernel<<<BLOCKS, THREADS>>>(node_rep, batch_ids, mol_idx, out, n_rows, rpw);
}